// round 9
// baseline (speedup 1.0000x reference)
#include <cuda_runtime.h>
#include <cuda_bf16.h>
#include <cstdint>

// ---------------------------------------------------------------------------
// GCN Q-Critic: 2x GCNConv(128->128) + concat(action 16) -> fc1(144->128) -> fc2(128->1)
// N = 100000, E = 1600000. edge_index = int32 [2, E].
//
// R8: tcgen05 is sm_103a-only and this harness compiles via compute_103 PTX,
// so GEMMs use warp-level mma.sync bf16 (HMMA) with split hi/lo fp32 emulation.
// CSR build + warp-per-node gather aggregation kept from R5.
// ---------------------------------------------------------------------------

#define MAX_N 100000
#define MAX_E 1700000
#define DIM   128

__device__ float g_bufA[MAX_N * DIM];
__device__ float g_bufB[MAX_N * DIM];
__device__ float g_dinv[MAX_N];
__device__ int   g_deg[MAX_N];
__device__ int   g_row[MAX_N + 1];
__device__ int   g_cursor[MAX_N];
__device__ int   g_csr_src[MAX_E];
__device__ int   g_bsum[1024];

__device__ __forceinline__ float* resolve(int sel) {
    return (sel == 1) ? g_bufA : g_bufB;
}
__device__ __forceinline__ int clampi(int v, int n) {
    return min(max(v, 0), n - 1);
}

// ===========================================================================
// CSR build (unchanged from R5)
// ===========================================================================
__global__ __launch_bounds__(256) void k_zero_deg(int n) {
    int i = blockIdx.x * blockDim.x + threadIdx.x;
    if (i < n) g_deg[i] = 0;
}
__global__ __launch_bounds__(256) void k_count_deg(const int* __restrict__ ei,
                                                   int n_edges, int n) {
    int e = blockIdx.x * blockDim.x + threadIdx.x;
    if (e < n_edges) atomicAdd(&g_deg[clampi(ei[n_edges + e], n)], 1);
}
__global__ __launch_bounds__(256) void k_dinv(int n) {
    int i = blockIdx.x * blockDim.x + threadIdx.x;
    if (i < n) g_dinv[i] = rsqrtf((float)(g_deg[i] + 1));
}
__global__ __launch_bounds__(256) void k_scan1(int n) {
    __shared__ int sm[256];
    int i = blockIdx.x * 256 + threadIdx.x;
    int v = (i < n) ? g_deg[i] : 0;
    sm[threadIdx.x] = v;
    __syncthreads();
#pragma unroll
    for (int off = 1; off < 256; off <<= 1) {
        int t = (threadIdx.x >= off) ? sm[threadIdx.x - off] : 0;
        __syncthreads();
        sm[threadIdx.x] += t;
        __syncthreads();
    }
    if (i < n) g_row[i] = sm[threadIdx.x] - v;
    if (threadIdx.x == 255) g_bsum[blockIdx.x] = sm[255];
}
__global__ __launch_bounds__(1024) void k_scan2(int nb) {
    __shared__ int sm[1024];
    int t = threadIdx.x;
    int v = (t < nb) ? g_bsum[t] : 0;
    sm[t] = v;
    __syncthreads();
#pragma unroll
    for (int off = 1; off < 1024; off <<= 1) {
        int u = (t >= off) ? sm[t - off] : 0;
        __syncthreads();
        sm[t] += u;
        __syncthreads();
    }
    if (t < nb) g_bsum[t] = sm[t] - v;
}
__global__ __launch_bounds__(256) void k_scan3(int n, int n_edges) {
    int i = blockIdx.x * 256 + threadIdx.x;
    if (i < n) {
        int r = g_row[i] + g_bsum[blockIdx.x];
        g_row[i] = r;
        g_cursor[i] = r;
    }
    if (i == 0) g_row[n] = n_edges;
}
__global__ __launch_bounds__(256) void k_fill(const int* __restrict__ ei,
                                              int n_edges, int n) {
    int e = blockIdx.x * blockDim.x + threadIdx.x;
    if (e < n_edges) {
        int s = clampi(ei[e], n);
        int d = clampi(ei[n_edges + e], n);
        int pos = atomicAdd(&g_cursor[d], 1);
        g_csr_src[pos] = s;
    }
}

// ===========================================================================
// Split fp32 -> bf16 hi/lo (packed pairs)
// ===========================================================================
__device__ __forceinline__ void split2(float v0, float v1,
                                       uint32_t& hi, uint32_t& lo) {
    __nv_bfloat16 h0 = __float2bfloat16(v0), h1 = __float2bfloat16(v1);
    float l0 = v0 - __bfloat162float(h0);
    float l1 = v1 - __bfloat162float(h1);
    __nv_bfloat16 g0 = __float2bfloat16(l0), g1 = __float2bfloat16(l1);
    hi = ((uint32_t)__bfloat16_as_ushort(h1) << 16) | __bfloat16_as_ushort(h0);
    lo = ((uint32_t)__bfloat16_as_ushort(g1) << 16) | __bfloat16_as_ushort(g0);
}

#define MMA16816(c, a, b0_, b1_)                                             \
    asm volatile(                                                            \
        "mma.sync.aligned.m16n8k16.row.col.f32.bf16.bf16.f32 "               \
        "{%0,%1,%2,%3}, {%4,%5,%6,%7}, {%8,%9}, {%0,%1,%2,%3};"              \
        : "+f"((c)[0]), "+f"((c)[1]), "+f"((c)[2]), "+f"((c)[3])             \
        : "r"((a)[0]), "r"((a)[1]), "r"((a)[2]), "r"((a)[3]),                \
          "r"(b0_), "r"(b1_))

// SMEM layout: u32 words, stride S per row (bf16-pair index space)
#define SSTRIDE 73
#define OFF_AH  0
#define OFF_AL  (OFF_AH + 128 * SSTRIDE)
#define OFF_BH  (OFF_AL + 128 * SSTRIDE)
#define OFF_BL  (OFF_BH + 128 * SSTRIDE)
#define OFF_RED (OFF_BL + 128 * SSTRIDE)          // 256 floats
#define SM_WORDS (OFF_RED + 256)
#define SM_BYTES (SM_WORDS * 4)

// ===========================================================================
// Tensor-core GEMM tile kernel (mma.sync bf16 split).
//   C[M,128] = f(A)[M,K] @ Wfull[K,128], K = nkc*16 (128 or 144).
//   A cols 0..127 from A (with optional in_bias+relu); cols 128..143 from action.
//   epilogue: q_out==null -> C = acc * (dinv[row] if scale_dinv)
//             q_out!=null -> h = relu(acc + fb1), q = h . fw2 + fb2
// 256 threads = 8 warps arranged 4(M) x 2(N); warp tile 32x64.
// ===========================================================================
__global__ __launch_bounds__(256) void k_gemm_mma(const float* __restrict__ Aext,
                                                  int a_sel,
                                                  const float* __restrict__ W,
                                                  const float* __restrict__ in_bias,
                                                  int c_sel, int M, int nkc,
                                                  int scale_dinv,
                                                  const float* __restrict__ action,
                                                  const float* __restrict__ fb1,
                                                  const float* __restrict__ fw2,
                                                  const float* __restrict__ fb2,
                                                  float* __restrict__ q_out) {
    extern __shared__ uint32_t smw[];
    uint32_t* sAh = smw + OFF_AH;
    uint32_t* sAl = smw + OFF_AL;
    uint32_t* sBh = smw + OFF_BH;
    uint32_t* sBl = smw + OFF_BL;
    float*    red = (float*)(smw + OFF_RED);

    const float* A = (a_sel == 0) ? Aext : resolve(a_sel);
    float*       C = resolve(c_sel);

    int tid    = threadIdx.x;
    int lane   = tid & 31;
    int wid    = tid >> 5;
    int warp_m = wid >> 1;
    int warp_n = wid & 1;
    int m0     = blockIdx.x * 128;

    // ---- conversion prologue ----
    {
        int r    = tid >> 1;          // 0..127 (row for A, col n for B)
        int half = tid & 1;
        int grow = clampi(m0 + r, M);
        int kpb  = half * nkc * 4;
        int kpe  = kpb + nkc * 4;

        // A tile -> sAh/sAl  (row r, bf16-pair kp)
        for (int kp = kpb; kp < kpe; kp++) {
            int k = kp * 2;
            float v0, v1;
            if (k < DIM) {
                v0 = A[(size_t)grow * DIM + k];
                v1 = A[(size_t)grow * DIM + k + 1];
                if (in_bias) {
                    v0 = fmaxf(v0 + in_bias[k], 0.0f);
                    v1 = fmaxf(v1 + in_bias[k + 1], 0.0f);
                }
            } else {
                v0 = action[(size_t)grow * 16 + (k - DIM)];
                v1 = action[(size_t)grow * 16 + (k - DIM) + 1];
            }
            uint32_t h, l;
            split2(v0, v1, h, l);
            sAh[r * SSTRIDE + kp] = h;
            sAl[r * SSTRIDE + kp] = l;
        }

        // B tile: W[K,128] transposed -> sB[n][kp]
        int n = r;
        for (int kp = kpb; kp < kpe; kp++) {
            int k = kp * 2;
            float w0 = W[(size_t)k * DIM + n];
            float w1 = W[(size_t)(k + 1) * DIM + n];
            uint32_t h, l;
            split2(w0, w1, h, l);
            sBh[n * SSTRIDE + kp] = h;
            sBl[n * SSTRIDE + kp] = l;
        }
    }
    __syncthreads();

    // ---- mma mainloop ----
    float acc[2][8][4];
#pragma unroll
    for (int mt = 0; mt < 2; mt++)
#pragma unroll
        for (int nt = 0; nt < 8; nt++)
#pragma unroll
            for (int j = 0; j < 4; j++) acc[mt][nt][j] = 0.0f;

    int q  = lane & 3;
    int rl = lane >> 2;

    for (int kc = 0; kc < nkc; kc++) {
        int kp0 = kc * 8;
        uint32_t ah[2][4], al[2][4];
#pragma unroll
        for (int mt = 0; mt < 2; mt++) {
            int row = warp_m * 32 + mt * 16 + rl;
            ah[mt][0] = sAh[row * SSTRIDE + kp0 + q];
            ah[mt][1] = sAh[(row + 8) * SSTRIDE + kp0 + q];
            ah[mt][2] = sAh[row * SSTRIDE + kp0 + 4 + q];
            ah[mt][3] = sAh[(row + 8) * SSTRIDE + kp0 + 4 + q];
            al[mt][0] = sAl[row * SSTRIDE + kp0 + q];
            al[mt][1] = sAl[(row + 8) * SSTRIDE + kp0 + q];
            al[mt][2] = sAl[row * SSTRIDE + kp0 + 4 + q];
            al[mt][3] = sAl[(row + 8) * SSTRIDE + kp0 + 4 + q];
        }
#pragma unroll
        for (int nt = 0; nt < 8; nt++) {
            int n = warp_n * 64 + nt * 8 + rl;
            uint32_t bh0 = sBh[n * SSTRIDE + kp0 + q];
            uint32_t bh1 = sBh[n * SSTRIDE + kp0 + 4 + q];
            uint32_t bl0 = sBl[n * SSTRIDE + kp0 + q];
            uint32_t bl1 = sBl[n * SSTRIDE + kp0 + 4 + q];
#pragma unroll
            for (int mt = 0; mt < 2; mt++) {
                MMA16816(acc[mt][nt], ah[mt], bh0, bh1);  // hi*hi
                MMA16816(acc[mt][nt], ah[mt], bl0, bl1);  // hi*lo
                MMA16816(acc[mt][nt], al[mt], bh0, bh1);  // lo*hi
            }
        }
    }

    // ---- epilogue ----
    if (q_out == nullptr) {
#pragma unroll
        for (int mt = 0; mt < 2; mt++) {
            int row_lo = m0 + warp_m * 32 + mt * 16 + rl;
            int row_hi = row_lo + 8;
            float s_lo = (row_lo < M && scale_dinv) ? g_dinv[row_lo] : 1.0f;
            float s_hi = (row_hi < M && scale_dinv) ? g_dinv[row_hi] : 1.0f;
#pragma unroll
            for (int nt = 0; nt < 8; nt++) {
                int col = warp_n * 64 + nt * 8 + q * 2;
                if (row_lo < M) {
                    float2 o = make_float2(acc[mt][nt][0] * s_lo,
                                           acc[mt][nt][1] * s_lo);
                    *reinterpret_cast<float2*>(C + (size_t)row_lo * DIM + col) = o;
                }
                if (row_hi < M) {
                    float2 o = make_float2(acc[mt][nt][2] * s_hi,
                                           acc[mt][nt][3] * s_hi);
                    *reinterpret_cast<float2*>(C + (size_t)row_hi * DIM + col) = o;
                }
            }
        }
    } else {
        // fused fc1 (bias+relu) + fc2 (dot) -> q
        float p[2][2] = {{0.f, 0.f}, {0.f, 0.f}};  // [mt][row_lo/row_hi]
#pragma unroll
        for (int mt = 0; mt < 2; mt++) {
#pragma unroll
            for (int nt = 0; nt < 8; nt++) {
                int col = warp_n * 64 + nt * 8 + q * 2;
                float b0 = fb1[col],     b1 = fb1[col + 1];
                float w0 = fw2[col],     w1 = fw2[col + 1];
                float h;
                h = fmaxf(acc[mt][nt][0] + b0, 0.0f); p[mt][0] = fmaf(h, w0, p[mt][0]);
                h = fmaxf(acc[mt][nt][1] + b1, 0.0f); p[mt][0] = fmaf(h, w1, p[mt][0]);
                h = fmaxf(acc[mt][nt][2] + b0, 0.0f); p[mt][1] = fmaf(h, w0, p[mt][1]);
                h = fmaxf(acc[mt][nt][3] + b1, 0.0f); p[mt][1] = fmaf(h, w1, p[mt][1]);
            }
        }
        // reduce over the 4 lanes sharing a row (lane&3 group)
#pragma unroll
        for (int mt = 0; mt < 2; mt++) {
#pragma unroll
            for (int hlf = 0; hlf < 2; hlf++) {
                p[mt][hlf] += __shfl_xor_sync(0xFFFFFFFFu, p[mt][hlf], 1);
                p[mt][hlf] += __shfl_xor_sync(0xFFFFFFFFu, p[mt][hlf], 2);
            }
        }
        if (q == 0) {
#pragma unroll
            for (int mt = 0; mt < 2; mt++) {
                int rloc = warp_m * 32 + mt * 16 + rl;
                red[rloc * 2 + warp_n]       = p[mt][0];
                red[(rloc + 8) * 2 + warp_n] = p[mt][1];
            }
        }
        __syncthreads();
        if (tid < 128) {
            int row = m0 + tid;
            if (row < M)
                q_out[row] = red[tid * 2] + red[tid * 2 + 1] + fb2[0];
        }
    }
}

// ===========================================================================
// Gather-aggregate (unchanged from R5): warp per node.
// out[v] = dinv[v] * ( y[v] + sum_{src in CSR(v)} y[src] )
// ===========================================================================
__global__ __launch_bounds__(256) void k_aggregate(int y_sel, int out_sel, int n) {
    const float* y   = resolve(y_sel);
    float*       out = resolve(out_sel);
    int t = blockIdx.x * blockDim.x + threadIdx.x;
    int v = t >> 5;
    int lane = t & 31;
    if (v >= n) return;

    int beg = g_row[v];
    int end = g_row[v + 1];

    float4 acc = reinterpret_cast<const float4*>(y + (size_t)v * DIM)[lane];

    for (int base = beg; base < end; base += 32) {
        int idx = base + lane;
        int sv = (idx < end) ? g_csr_src[idx] : 0;
        int cnt = min(32, end - base);
        int j = 0;
        for (; j + 4 <= cnt; j += 4) {
            int s0 = __shfl_sync(0xFFFFFFFFu, sv, j);
            int s1 = __shfl_sync(0xFFFFFFFFu, sv, j + 1);
            int s2 = __shfl_sync(0xFFFFFFFFu, sv, j + 2);
            int s3 = __shfl_sync(0xFFFFFFFFu, sv, j + 3);
            float4 t0 = reinterpret_cast<const float4*>(y + (size_t)s0 * DIM)[lane];
            float4 t1 = reinterpret_cast<const float4*>(y + (size_t)s1 * DIM)[lane];
            float4 t2 = reinterpret_cast<const float4*>(y + (size_t)s2 * DIM)[lane];
            float4 t3 = reinterpret_cast<const float4*>(y + (size_t)s3 * DIM)[lane];
            acc.x += t0.x + t1.x + t2.x + t3.x;
            acc.y += t0.y + t1.y + t2.y + t3.y;
            acc.z += t0.z + t1.z + t2.z + t3.z;
            acc.w += t0.w + t1.w + t2.w + t3.w;
        }
        for (; j < cnt; j++) {
            int s = __shfl_sync(0xFFFFFFFFu, sv, j);
            float4 tv = reinterpret_cast<const float4*>(y + (size_t)s * DIM)[lane];
            acc.x += tv.x; acc.y += tv.y; acc.z += tv.z; acc.w += tv.w;
        }
    }

    float dd = g_dinv[v];
    acc.x *= dd; acc.y *= dd; acc.z *= dd; acc.w *= dd;
    reinterpret_cast<float4*>(out + (size_t)v * DIM)[lane] = acc;
}

// ===========================================================================
// Host launcher
// ===========================================================================
extern "C" void kernel_launch(void* const* d_in, const int* in_sizes, int n_in,
                              void* d_out, int out_size) {
    const float* x      = (const float*)d_in[0];
    const int*   ei     = (const int*)d_in[1];
    const float* action = (const float*)d_in[2];
    const float* w1     = (const float*)d_in[3];
    const float* b1     = (const float*)d_in[4];
    const float* w2     = (const float*)d_in[5];
    const float* b2     = (const float*)d_in[6];
    const float* fw1    = (const float*)d_in[7];
    const float* fb1    = (const float*)d_in[8];
    const float* fw2    = (const float*)d_in[9];
    const float* fb2    = (const float*)d_in[10];

    int N = in_sizes[0] / DIM;
    int E = in_sizes[1] / 2;

    int nb256       = (N + 255) / 256;
    int eb256       = (E + 255) / 256;
    int gemm_blocks = (N + 127) / 128;
    int agg_blocks  = (int)(((long long)N * 32 + 255) / 256);

    cudaFuncSetAttribute(k_gemm_mma, cudaFuncAttributeMaxDynamicSharedMemorySize,
                         SM_BYTES);

    // ---- CSR build + dinv ----
    k_zero_deg <<<nb256, 256>>>(N);
    k_count_deg<<<eb256, 256>>>(ei, E, N);
    k_dinv     <<<nb256, 256>>>(N);
    k_scan1    <<<nb256, 256>>>(N);
    k_scan2    <<<1, 1024>>>(nb256);
    k_scan3    <<<nb256, 256>>>(N, E);
    k_fill     <<<eb256, 256>>>(ei, E, N);

    // ---- GCN layer 1 ----  y1 = (x@W1)*dinv -> bufA; aggregate -> bufB
    k_gemm_mma <<<gemm_blocks, 256, SM_BYTES>>>(x, 0, w1, nullptr,
                                                1, N, 8, 1,
                                                nullptr, nullptr, nullptr, nullptr,
                                                nullptr);
    k_aggregate<<<agg_blocks, 256>>>(1, 2, N);

    // ---- GCN layer 2 ----  y2 = (relu(agg1+b1)@W2)*dinv -> bufA; aggregate -> bufB
    k_gemm_mma <<<gemm_blocks, 256, SM_BYTES>>>(nullptr, 2, w2, b1,
                                                1, N, 8, 1,
                                                nullptr, nullptr, nullptr, nullptr,
                                                nullptr);
    k_aggregate<<<agg_blocks, 256>>>(1, 2, N);

    // ---- MLP head ----  q = relu([relu(agg2+b2), action]@fw1 + fb1) . fw2 + fb2
    k_gemm_mma<<<gemm_blocks, 256, SM_BYTES>>>(nullptr, 2, fw1, b2,
                                               1, N, 9, 0,
                                               action, fb1, fw2, fb2,
                                               (float*)d_out);
}

// round 12
// speedup vs baseline: 1.1229x; 1.1229x over previous
#include <cuda_runtime.h>
#include <cstdint>

// ---------------------------------------------------------------------------
// GCN Q-Critic: 2x GCNConv(128->128) + concat(action 16) -> fc1(144->128) -> fc2(128->1)
// N = 100000, E = 1600000. edge_index = int32 [2, E].
//
// R9: back to the R5 fp32 SGEMM skeleton, inner product converted to packed
// fma.rn.f32x2 (Blackwell FFMA2: 2 fp32 FMAs per FMA-pipe issue slot).
// CSR build + warp-per-node gather aggregation unchanged from R5.
// ---------------------------------------------------------------------------

#define MAX_N 100000
#define MAX_E 1700000
#define DIM   128

typedef unsigned long long u64;

#define PACK2(dst, x, y) \
    asm("mov.b64 %0, {%1, %2};" : "=l"(dst) : "f"(x), "f"(y))
#define FMA2(acc, a, b) \
    asm("fma.rn.f32x2 %0, %1, %2, %0;" : "+l"(acc) : "l"(a), "l"(b))
#define UNPACK2(x, y, src) \
    asm("mov.b64 {%0, %1}, %2;" : "=f"(x), "=f"(y) : "l"(src))

__device__ float g_bufA[MAX_N * DIM];
__device__ float g_bufB[MAX_N * DIM];
__device__ float g_dinv[MAX_N];
__device__ int   g_deg[MAX_N];
__device__ int   g_row[MAX_N + 1];
__device__ int   g_cursor[MAX_N];
__device__ int   g_csr_src[MAX_E];
__device__ int   g_bsum[1024];

__device__ __forceinline__ float* resolve(int sel) {
    return (sel == 1) ? g_bufA : g_bufB;
}
__device__ __forceinline__ int clampi(int v, int n) {
    return min(max(v, 0), n - 1);
}

// ===========================================================================
// CSR build (unchanged from R5)
// ===========================================================================
__global__ __launch_bounds__(256) void k_zero_deg(int n) {
    int i = blockIdx.x * blockDim.x + threadIdx.x;
    if (i < n) g_deg[i] = 0;
}
__global__ __launch_bounds__(256) void k_count_deg(const int* __restrict__ ei,
                                                   int n_edges, int n) {
    int e = blockIdx.x * blockDim.x + threadIdx.x;
    if (e < n_edges) atomicAdd(&g_deg[clampi(ei[n_edges + e], n)], 1);
}
__global__ __launch_bounds__(256) void k_dinv(int n) {
    int i = blockIdx.x * blockDim.x + threadIdx.x;
    if (i < n) g_dinv[i] = rsqrtf((float)(g_deg[i] + 1));
}
__global__ __launch_bounds__(256) void k_scan1(int n) {
    __shared__ int sm[256];
    int i = blockIdx.x * 256 + threadIdx.x;
    int v = (i < n) ? g_deg[i] : 0;
    sm[threadIdx.x] = v;
    __syncthreads();
#pragma unroll
    for (int off = 1; off < 256; off <<= 1) {
        int t = (threadIdx.x >= off) ? sm[threadIdx.x - off] : 0;
        __syncthreads();
        sm[threadIdx.x] += t;
        __syncthreads();
    }
    if (i < n) g_row[i] = sm[threadIdx.x] - v;
    if (threadIdx.x == 255) g_bsum[blockIdx.x] = sm[255];
}
__global__ __launch_bounds__(1024) void k_scan2(int nb) {
    __shared__ int sm[1024];
    int t = threadIdx.x;
    int v = (t < nb) ? g_bsum[t] : 0;
    sm[t] = v;
    __syncthreads();
#pragma unroll
    for (int off = 1; off < 1024; off <<= 1) {
        int u = (t >= off) ? sm[t - off] : 0;
        __syncthreads();
        sm[t] += u;
        __syncthreads();
    }
    if (t < nb) g_bsum[t] = sm[t] - v;
}
__global__ __launch_bounds__(256) void k_scan3(int n, int n_edges) {
    int i = blockIdx.x * 256 + threadIdx.x;
    if (i < n) {
        int r = g_row[i] + g_bsum[blockIdx.x];
        g_row[i] = r;
        g_cursor[i] = r;
    }
    if (i == 0) g_row[n] = n_edges;
}
__global__ __launch_bounds__(256) void k_fill(const int* __restrict__ ei,
                                              int n_edges, int n) {
    int e = blockIdx.x * blockDim.x + threadIdx.x;
    if (e < n_edges) {
        int s = clampi(ei[e], n);
        int d = clampi(ei[n_edges + e], n);
        int pos = atomicAdd(&g_cursor[d], 1);
        g_csr_src[pos] = s;
    }
}

// ===========================================================================
// SGEMM (f32x2 inner product): C[M,128] = f(A)[M,K] @ W[K,128]
//   f(A): if in_bias != null, main-region A becomes relu(a + in_bias[col])
//   A2 supplies cols 128..K-1 (action concat, stride 16)
//   epilogue: q_out==null -> C = acc * (dinv[row] if scale_dinv)
//             q_out!=null -> fused fc1(bias+relu)+fc2(dot) -> q_out
// BM=128, BN=128, BK=16, 256 threads; thread tile 8x8 held as 4 row-pairs x 8.
// ===========================================================================
__global__ __launch_bounds__(256) void k_sgemm(const float* __restrict__ Aext,
                                               int a_sel,
                                               const float* __restrict__ A2,
                                               const float* __restrict__ W,
                                               const float* __restrict__ in_bias,
                                               int c_sel,
                                               int M, int K, int scale_dinv,
                                               const float* __restrict__ fc1_b,
                                               const float* __restrict__ fc2_w,
                                               const float* __restrict__ fc2_b,
                                               float* __restrict__ q_out) {
    const float* A = (a_sel == 0) ? Aext : resolve(a_sel);
    float*       C = resolve(c_sel);

    __shared__ float As[16][DIM + 4];
    __shared__ float Bs[16][DIM];
    __shared__ float Red[128][17];

    int tid = threadIdx.x;
    int m0  = blockIdx.x * 128;
    int tm = (tid >> 4) * 8;
    int tn = (tid & 15) * 8;

    // acc2[ip][j] packs rows (tm+2ip, tm+2ip+1), col tn+j
    u64 acc2[4][8];
#pragma unroll
    for (int ip = 0; ip < 4; ip++)
#pragma unroll
        for (int j = 0; j < 8; j++) acc2[ip][j] = 0ull;

    int ar = tid >> 1;
    int ak = (tid & 1) * 8;
    int gm = m0 + ar;
    int bk = tid >> 5;
    int bn = (tid & 31) * 4;

    int n_tiles = K / 16;
    for (int t = 0; t < n_tiles; t++) {
        int k0 = t * 16;
        float av[8];
        if (gm < M) {
            if (k0 < DIM) {
                const float4* p = reinterpret_cast<const float4*>(A + (size_t)gm * DIM + k0 + ak);
                float4 v0 = p[0], v1 = p[1];
                av[0]=v0.x; av[1]=v0.y; av[2]=v0.z; av[3]=v0.w;
                av[4]=v1.x; av[5]=v1.y; av[6]=v1.z; av[7]=v1.w;
                if (in_bias) {
                    const float4* bp = reinterpret_cast<const float4*>(in_bias + k0 + ak);
                    float4 b0 = bp[0], b1 = bp[1];
                    av[0]=fmaxf(av[0]+b0.x,0.f); av[1]=fmaxf(av[1]+b0.y,0.f);
                    av[2]=fmaxf(av[2]+b0.z,0.f); av[3]=fmaxf(av[3]+b0.w,0.f);
                    av[4]=fmaxf(av[4]+b1.x,0.f); av[5]=fmaxf(av[5]+b1.y,0.f);
                    av[6]=fmaxf(av[6]+b1.z,0.f); av[7]=fmaxf(av[7]+b1.w,0.f);
                }
            } else {
                const float4* p = reinterpret_cast<const float4*>(A2 + (size_t)gm * 16 + (k0 - DIM) + ak);
                float4 v0 = p[0], v1 = p[1];
                av[0]=v0.x; av[1]=v0.y; av[2]=v0.z; av[3]=v0.w;
                av[4]=v1.x; av[5]=v1.y; av[6]=v1.z; av[7]=v1.w;
            }
        } else {
#pragma unroll
            for (int i = 0; i < 8; i++) av[i] = 0.0f;
        }
#pragma unroll
        for (int i = 0; i < 8; i++) As[ak + i][ar] = av[i];

        {
            const float4* p0 = reinterpret_cast<const float4*>(W + (size_t)(k0 + bk) * DIM + bn);
            const float4* p1 = reinterpret_cast<const float4*>(W + (size_t)(k0 + bk + 8) * DIM + bn);
            *reinterpret_cast<float4*>(&Bs[bk][bn])     = *p0;
            *reinterpret_cast<float4*>(&Bs[bk + 8][bn]) = *p1;
        }
        __syncthreads();

#pragma unroll
        for (int k = 0; k < 16; k++) {
            float4 a0 = *reinterpret_cast<const float4*>(&As[k][tm]);
            float4 a1 = *reinterpret_cast<const float4*>(&As[k][tm + 4]);
            float4 b0 = *reinterpret_cast<const float4*>(&Bs[k][tn]);
            float4 b1 = *reinterpret_cast<const float4*>(&Bs[k][tn + 4]);

            u64 ap[4];
            PACK2(ap[0], a0.x, a0.y);
            PACK2(ap[1], a0.z, a0.w);
            PACK2(ap[2], a1.x, a1.y);
            PACK2(ap[3], a1.z, a1.w);

            u64 bb[8];
            PACK2(bb[0], b0.x, b0.x);
            PACK2(bb[1], b0.y, b0.y);
            PACK2(bb[2], b0.z, b0.z);
            PACK2(bb[3], b0.w, b0.w);
            PACK2(bb[4], b1.x, b1.x);
            PACK2(bb[5], b1.y, b1.y);
            PACK2(bb[6], b1.z, b1.z);
            PACK2(bb[7], b1.w, b1.w);

#pragma unroll
            for (int ip = 0; ip < 4; ip++)
#pragma unroll
                for (int j = 0; j < 8; j++)
                    FMA2(acc2[ip][j], ap[ip], bb[j]);
        }
        __syncthreads();
    }

    // unpack acc2 -> acc[8][8]
    float acc[8][8];
#pragma unroll
    for (int ip = 0; ip < 4; ip++)
#pragma unroll
        for (int j = 0; j < 8; j++)
            UNPACK2(acc[2 * ip][j], acc[2 * ip + 1][j], acc2[ip][j]);

    if (q_out == nullptr) {
#pragma unroll
        for (int i = 0; i < 8; i++) {
            int row = m0 + tm + i;
            if (row < M) {
                float s = scale_dinv ? g_dinv[row] : 1.0f;
                float4 o0, o1;
                o0.x=acc[i][0]*s; o0.y=acc[i][1]*s; o0.z=acc[i][2]*s; o0.w=acc[i][3]*s;
                o1.x=acc[i][4]*s; o1.y=acc[i][5]*s; o1.z=acc[i][6]*s; o1.w=acc[i][7]*s;
                float4* cp = reinterpret_cast<float4*>(C + (size_t)row * DIM + tn);
                cp[0]=o0; cp[1]=o1;
            }
        }
    } else {
        float fb[8], fw[8];
#pragma unroll
        for (int j = 0; j < 8; j++) { fb[j] = fc1_b[tn + j]; fw[j] = fc2_w[tn + j]; }
#pragma unroll
        for (int i = 0; i < 8; i++) {
            float p = 0.0f;
#pragma unroll
            for (int j = 0; j < 8; j++) {
                float h = fmaxf(acc[i][j] + fb[j], 0.0f);
                p = fmaf(h, fw[j], p);
            }
            Red[tm + i][tid & 15] = p;
        }
        __syncthreads();
        if (tid < 128) {
            int row = m0 + tid;
            if (row < M) {
                float s = fc2_b[0];
#pragma unroll
                for (int j = 0; j < 16; j++) s += Red[tid][j];
                q_out[row] = s;
            }
        }
    }
}

// ===========================================================================
// Gather-aggregate (unchanged from R5): warp per node.
// out[v] = dinv[v] * ( y[v] + sum_{src in CSR(v)} y[src] )
// ===========================================================================
__global__ __launch_bounds__(256) void k_aggregate(int y_sel, int out_sel, int n) {
    const float* y   = resolve(y_sel);
    float*       out = resolve(out_sel);
    int t = blockIdx.x * blockDim.x + threadIdx.x;
    int v = t >> 5;
    int lane = t & 31;
    if (v >= n) return;

    int beg = g_row[v];
    int end = g_row[v + 1];

    float4 acc = reinterpret_cast<const float4*>(y + (size_t)v * DIM)[lane];

    for (int base = beg; base < end; base += 32) {
        int idx = base + lane;
        int sv = (idx < end) ? g_csr_src[idx] : 0;
        int cnt = min(32, end - base);
        int j = 0;
        for (; j + 4 <= cnt; j += 4) {
            int s0 = __shfl_sync(0xFFFFFFFFu, sv, j);
            int s1 = __shfl_sync(0xFFFFFFFFu, sv, j + 1);
            int s2 = __shfl_sync(0xFFFFFFFFu, sv, j + 2);
            int s3 = __shfl_sync(0xFFFFFFFFu, sv, j + 3);
            float4 t0 = reinterpret_cast<const float4*>(y + (size_t)s0 * DIM)[lane];
            float4 t1 = reinterpret_cast<const float4*>(y + (size_t)s1 * DIM)[lane];
            float4 t2 = reinterpret_cast<const float4*>(y + (size_t)s2 * DIM)[lane];
            float4 t3 = reinterpret_cast<const float4*>(y + (size_t)s3 * DIM)[lane];
            acc.x += t0.x + t1.x + t2.x + t3.x;
            acc.y += t0.y + t1.y + t2.y + t3.y;
            acc.z += t0.z + t1.z + t2.z + t3.z;
            acc.w += t0.w + t1.w + t2.w + t3.w;
        }
        for (; j < cnt; j++) {
            int s = __shfl_sync(0xFFFFFFFFu, sv, j);
            float4 tv = reinterpret_cast<const float4*>(y + (size_t)s * DIM)[lane];
            acc.x += tv.x; acc.y += tv.y; acc.z += tv.z; acc.w += tv.w;
        }
    }

    float dd = g_dinv[v];
    acc.x *= dd; acc.y *= dd; acc.z *= dd; acc.w *= dd;
    reinterpret_cast<float4*>(out + (size_t)v * DIM)[lane] = acc;
}

// ===========================================================================
// Host launcher
// ===========================================================================
extern "C" void kernel_launch(void* const* d_in, const int* in_sizes, int n_in,
                              void* d_out, int out_size) {
    const float* x      = (const float*)d_in[0];
    const int*   ei     = (const int*)d_in[1];
    const float* action = (const float*)d_in[2];
    const float* w1     = (const float*)d_in[3];
    const float* b1     = (const float*)d_in[4];
    const float* w2     = (const float*)d_in[5];
    const float* b2     = (const float*)d_in[6];
    const float* fw1    = (const float*)d_in[7];
    const float* fb1    = (const float*)d_in[8];
    const float* fw2    = (const float*)d_in[9];
    const float* fb2    = (const float*)d_in[10];

    int N = in_sizes[0] / DIM;
    int E = in_sizes[1] / 2;

    int nb256       = (N + 255) / 256;
    int eb256       = (E + 255) / 256;
    int gemm_blocks = (N + 127) / 128;
    int agg_blocks  = (int)(((long long)N * 32 + 255) / 256);

    // ---- CSR build + dinv ----
    k_zero_deg <<<nb256, 256>>>(N);
    k_count_deg<<<eb256, 256>>>(ei, E, N);
    k_dinv     <<<nb256, 256>>>(N);
    k_scan1    <<<nb256, 256>>>(N);
    k_scan2    <<<1, 1024>>>(nb256);
    k_scan3    <<<nb256, 256>>>(N, E);
    k_fill     <<<eb256, 256>>>(ei, E, N);

    // ---- GCN layer 1 ----  y1 = (x@W1)*dinv -> bufA; aggregate -> bufB
    k_sgemm    <<<gemm_blocks, 256>>>(x, 0, nullptr, w1, nullptr,
                                      1, N, DIM, 1,
                                      nullptr, nullptr, nullptr, nullptr);
    k_aggregate<<<agg_blocks, 256>>>(1, 2, N);

    // ---- GCN layer 2 ----  y2 = (relu(agg1+b1)@W2)*dinv -> bufA; aggregate -> bufB
    k_sgemm    <<<gemm_blocks, 256>>>(nullptr, 2, nullptr, w2, b1,
                                      1, N, DIM, 1,
                                      nullptr, nullptr, nullptr, nullptr);
    k_aggregate<<<agg_blocks, 256>>>(1, 2, N);

    // ---- MLP head ----  q = relu([relu(agg2+b2), action]@fw1 + fb1) . fw2 + fb2
    k_sgemm<<<gemm_blocks, 256>>>(nullptr, 2, action, fw1, b2,
                                  1, N, DIM + 16, 0,
                                  fb1, fw2, fb2, (float*)d_out);
}

// round 13
// speedup vs baseline: 1.2601x; 1.1222x over previous
#include <cuda_runtime.h>
#include <cuda_fp16.h>
#include <cstdint>

// ---------------------------------------------------------------------------
// GCN Q-Critic: 2x GCNConv(128->128) + concat(action 16) -> fc1(144->128) -> fc2(128->1)
// N = 100000, E = 1600000. edge_index = int32 [2, E].
//
// R12: gather operand y stored as fp16 (halves L2 gather traffic in aggregate,
// which is at the LTS throughput cap). FFMA2 SGEMM kept from R9. k_dinv fused
// into scan1.
// ---------------------------------------------------------------------------

#define MAX_N 100000
#define MAX_E 1700000
#define DIM   128

typedef unsigned long long u64;

#define PACK2(dst, x, y) \
    asm("mov.b64 %0, {%1, %2};" : "=l"(dst) : "f"(x), "f"(y))
#define FMA2(acc, a, b) \
    asm("fma.rn.f32x2 %0, %1, %2, %0;" : "+l"(acc) : "l"(a), "l"(b))
#define UNPACK2(x, y, src) \
    asm("mov.b64 {%0, %1}, %2;" : "=f"(x), "=f"(y) : "l"(src))

__device__ __half g_bufH[MAX_N * DIM];   // y = (A@W)*dinv, fp16 (gather operand)
__device__ float  g_bufB[MAX_N * DIM];   // aggregated output, fp32
__device__ float  g_dinv[MAX_N];
__device__ int    g_deg[MAX_N];
__device__ int    g_row[MAX_N + 1];
__device__ int    g_cursor[MAX_N];
__device__ int    g_csr_src[MAX_E];
__device__ int    g_bsum[1024];

__device__ __forceinline__ int clampi(int v, int n) {
    return min(max(v, 0), n - 1);
}

// ===========================================================================
// CSR build
// ===========================================================================
__global__ __launch_bounds__(256) void k_zero_deg(int n) {
    int i = blockIdx.x * blockDim.x + threadIdx.x;
    if (i < n) g_deg[i] = 0;
}
__global__ __launch_bounds__(256) void k_count_deg(const int* __restrict__ ei,
                                                   int n_edges, int n) {
    int e = blockIdx.x * blockDim.x + threadIdx.x;
    if (e < n_edges) atomicAdd(&g_deg[clampi(ei[n_edges + e], n)], 1);
}
// scan stage 1 (+ fused dinv): per-block scan of degrees
__global__ __launch_bounds__(256) void k_scan1(int n) {
    __shared__ int sm[256];
    int i = blockIdx.x * 256 + threadIdx.x;
    int v = (i < n) ? g_deg[i] : 0;
    if (i < n) g_dinv[i] = rsqrtf((float)(v + 1));   // +1 self-loop
    sm[threadIdx.x] = v;
    __syncthreads();
#pragma unroll
    for (int off = 1; off < 256; off <<= 1) {
        int t = (threadIdx.x >= off) ? sm[threadIdx.x - off] : 0;
        __syncthreads();
        sm[threadIdx.x] += t;
        __syncthreads();
    }
    if (i < n) g_row[i] = sm[threadIdx.x] - v;
    if (threadIdx.x == 255) g_bsum[blockIdx.x] = sm[255];
}
__global__ __launch_bounds__(1024) void k_scan2(int nb) {
    __shared__ int sm[1024];
    int t = threadIdx.x;
    int v = (t < nb) ? g_bsum[t] : 0;
    sm[t] = v;
    __syncthreads();
#pragma unroll
    for (int off = 1; off < 1024; off <<= 1) {
        int u = (t >= off) ? sm[t - off] : 0;
        __syncthreads();
        sm[t] += u;
        __syncthreads();
    }
    if (t < nb) g_bsum[t] = sm[t] - v;
}
__global__ __launch_bounds__(256) void k_scan3(int n, int n_edges) {
    int i = blockIdx.x * 256 + threadIdx.x;
    if (i < n) {
        int r = g_row[i] + g_bsum[blockIdx.x];
        g_row[i] = r;
        g_cursor[i] = r;
    }
    if (i == 0) g_row[n] = n_edges;
}
__global__ __launch_bounds__(256) void k_fill(const int* __restrict__ ei,
                                              int n_edges, int n) {
    int e = blockIdx.x * blockDim.x + threadIdx.x;
    if (e < n_edges) {
        int s = clampi(ei[e], n);
        int d = clampi(ei[n_edges + e], n);
        int pos = atomicAdd(&g_cursor[d], 1);
        g_csr_src[pos] = s;
    }
}

// ===========================================================================
// SGEMM (f32x2 inner product): out = f(A)[M,K] @ W[K,128]
//   f(A): if in_bias != null, main-region A becomes relu(a + in_bias[col])
//   A2 supplies cols 128..K-1 (action concat, stride 16)
//   epilogue: q_out==null -> g_bufH[row] = half(acc * dinv[row])
//             q_out!=null -> fused fc1(bias+relu)+fc2(dot) -> q_out
// BM=128, BN=128, BK=16, 256 threads; 8x8 thread tile as 4 row-pairs x 8 f32x2.
// ===========================================================================
__global__ __launch_bounds__(256) void k_sgemm(const float* __restrict__ Aext,
                                               int a_sel,
                                               const float* __restrict__ A2,
                                               const float* __restrict__ W,
                                               const float* __restrict__ in_bias,
                                               int M, int K,
                                               const float* __restrict__ fc1_b,
                                               const float* __restrict__ fc2_w,
                                               const float* __restrict__ fc2_b,
                                               float* __restrict__ q_out) {
    const float* A = (a_sel == 0) ? Aext : g_bufB;

    __shared__ float As[16][DIM + 4];
    __shared__ float Bs[16][DIM];
    __shared__ float Red[128][17];

    int tid = threadIdx.x;
    int m0  = blockIdx.x * 128;
    int tm = (tid >> 4) * 8;
    int tn = (tid & 15) * 8;

    u64 acc2[4][8];
#pragma unroll
    for (int ip = 0; ip < 4; ip++)
#pragma unroll
        for (int j = 0; j < 8; j++) acc2[ip][j] = 0ull;

    int ar = tid >> 1;
    int ak = (tid & 1) * 8;
    int gm = m0 + ar;
    int bk = tid >> 5;
    int bn = (tid & 31) * 4;

    int n_tiles = K / 16;
    for (int t = 0; t < n_tiles; t++) {
        int k0 = t * 16;
        float av[8];
        if (gm < M) {
            if (k0 < DIM) {
                const float4* p = reinterpret_cast<const float4*>(A + (size_t)gm * DIM + k0 + ak);
                float4 v0 = p[0], v1 = p[1];
                av[0]=v0.x; av[1]=v0.y; av[2]=v0.z; av[3]=v0.w;
                av[4]=v1.x; av[5]=v1.y; av[6]=v1.z; av[7]=v1.w;
                if (in_bias) {
                    const float4* bp = reinterpret_cast<const float4*>(in_bias + k0 + ak);
                    float4 b0 = bp[0], b1 = bp[1];
                    av[0]=fmaxf(av[0]+b0.x,0.f); av[1]=fmaxf(av[1]+b0.y,0.f);
                    av[2]=fmaxf(av[2]+b0.z,0.f); av[3]=fmaxf(av[3]+b0.w,0.f);
                    av[4]=fmaxf(av[4]+b1.x,0.f); av[5]=fmaxf(av[5]+b1.y,0.f);
                    av[6]=fmaxf(av[6]+b1.z,0.f); av[7]=fmaxf(av[7]+b1.w,0.f);
                }
            } else {
                const float4* p = reinterpret_cast<const float4*>(A2 + (size_t)gm * 16 + (k0 - DIM) + ak);
                float4 v0 = p[0], v1 = p[1];
                av[0]=v0.x; av[1]=v0.y; av[2]=v0.z; av[3]=v0.w;
                av[4]=v1.x; av[5]=v1.y; av[6]=v1.z; av[7]=v1.w;
            }
        } else {
#pragma unroll
            for (int i = 0; i < 8; i++) av[i] = 0.0f;
        }
#pragma unroll
        for (int i = 0; i < 8; i++) As[ak + i][ar] = av[i];

        {
            const float4* p0 = reinterpret_cast<const float4*>(W + (size_t)(k0 + bk) * DIM + bn);
            const float4* p1 = reinterpret_cast<const float4*>(W + (size_t)(k0 + bk + 8) * DIM + bn);
            *reinterpret_cast<float4*>(&Bs[bk][bn])     = *p0;
            *reinterpret_cast<float4*>(&Bs[bk + 8][bn]) = *p1;
        }
        __syncthreads();

#pragma unroll
        for (int k = 0; k < 16; k++) {
            float4 a0 = *reinterpret_cast<const float4*>(&As[k][tm]);
            float4 a1 = *reinterpret_cast<const float4*>(&As[k][tm + 4]);
            float4 b0 = *reinterpret_cast<const float4*>(&Bs[k][tn]);
            float4 b1 = *reinterpret_cast<const float4*>(&Bs[k][tn + 4]);

            u64 ap[4];
            PACK2(ap[0], a0.x, a0.y);
            PACK2(ap[1], a0.z, a0.w);
            PACK2(ap[2], a1.x, a1.y);
            PACK2(ap[3], a1.z, a1.w);

            u64 bb[8];
            PACK2(bb[0], b0.x, b0.x);
            PACK2(bb[1], b0.y, b0.y);
            PACK2(bb[2], b0.z, b0.z);
            PACK2(bb[3], b0.w, b0.w);
            PACK2(bb[4], b1.x, b1.x);
            PACK2(bb[5], b1.y, b1.y);
            PACK2(bb[6], b1.z, b1.z);
            PACK2(bb[7], b1.w, b1.w);

#pragma unroll
            for (int ip = 0; ip < 4; ip++)
#pragma unroll
                for (int j = 0; j < 8; j++)
                    FMA2(acc2[ip][j], ap[ip], bb[j]);
        }
        __syncthreads();
    }

    float acc[8][8];
#pragma unroll
    for (int ip = 0; ip < 4; ip++)
#pragma unroll
        for (int j = 0; j < 8; j++)
            UNPACK2(acc[2 * ip][j], acc[2 * ip + 1][j], acc2[ip][j]);

    if (q_out == nullptr) {
        // y[row] = half(acc * dinv[row]) -> g_bufH (one 16B store per row)
#pragma unroll
        for (int i = 0; i < 8; i++) {
            int row = m0 + tm + i;
            if (row < M) {
                float s = g_dinv[row];
                __half2 h0 = __float22half2_rn(make_float2(acc[i][0]*s, acc[i][1]*s));
                __half2 h1 = __float22half2_rn(make_float2(acc[i][2]*s, acc[i][3]*s));
                __half2 h2 = __float22half2_rn(make_float2(acc[i][4]*s, acc[i][5]*s));
                __half2 h3 = __float22half2_rn(make_float2(acc[i][6]*s, acc[i][7]*s));
                uint4 o;
                o.x = *reinterpret_cast<uint32_t*>(&h0);
                o.y = *reinterpret_cast<uint32_t*>(&h1);
                o.z = *reinterpret_cast<uint32_t*>(&h2);
                o.w = *reinterpret_cast<uint32_t*>(&h3);
                *reinterpret_cast<uint4*>(g_bufH + (size_t)row * DIM + tn) = o;
            }
        }
    } else {
        float fb[8], fw[8];
#pragma unroll
        for (int j = 0; j < 8; j++) { fb[j] = fc1_b[tn + j]; fw[j] = fc2_w[tn + j]; }
#pragma unroll
        for (int i = 0; i < 8; i++) {
            float p = 0.0f;
#pragma unroll
            for (int j = 0; j < 8; j++) {
                float h = fmaxf(acc[i][j] + fb[j], 0.0f);
                p = fmaf(h, fw[j], p);
            }
            Red[tm + i][tid & 15] = p;
        }
        __syncthreads();
        if (tid < 128) {
            int row = m0 + tid;
            if (row < M) {
                float s = fc2_b[0];
#pragma unroll
                for (int j = 0; j < 16; j++) s += Red[tid][j];
                q_out[row] = s;
            }
        }
    }
}

// ===========================================================================
// Gather-aggregate: warp per node, fp16 gather operand.
// bufB[v] = dinv[v] * ( yH[v] + sum_{src in CSR(v)} yH[src] )
// Each lane covers 4 dims: one uint2 (4 halves, 8B) per row -> 256B/row coalesced.
// ===========================================================================
__global__ __launch_bounds__(256) void k_aggregate(int n) {
    int t = blockIdx.x * blockDim.x + threadIdx.x;
    int v = t >> 5;
    int lane = t & 31;
    if (v >= n) return;

    int beg = g_row[v];
    int end = g_row[v + 1];

    const uint2* yrow = reinterpret_cast<const uint2*>(g_bufH + (size_t)v * DIM);
    uint2 sp = yrow[lane];
    float2 f0 = __half22float2(*reinterpret_cast<const __half2*>(&sp.x));
    float2 f1 = __half22float2(*reinterpret_cast<const __half2*>(&sp.y));
    float4 acc = make_float4(f0.x, f0.y, f1.x, f1.y);

    for (int base = beg; base < end; base += 32) {
        int idx = base + lane;
        int sv = (idx < end) ? g_csr_src[idx] : 0;
        int cnt = min(32, end - base);
        int j = 0;
        for (; j + 4 <= cnt; j += 4) {
            int s0 = __shfl_sync(0xFFFFFFFFu, sv, j);
            int s1 = __shfl_sync(0xFFFFFFFFu, sv, j + 1);
            int s2 = __shfl_sync(0xFFFFFFFFu, sv, j + 2);
            int s3 = __shfl_sync(0xFFFFFFFFu, sv, j + 3);
            uint2 p0 = reinterpret_cast<const uint2*>(g_bufH + (size_t)s0 * DIM)[lane];
            uint2 p1 = reinterpret_cast<const uint2*>(g_bufH + (size_t)s1 * DIM)[lane];
            uint2 p2 = reinterpret_cast<const uint2*>(g_bufH + (size_t)s2 * DIM)[lane];
            uint2 p3 = reinterpret_cast<const uint2*>(g_bufH + (size_t)s3 * DIM)[lane];
            float2 a0 = __half22float2(*reinterpret_cast<const __half2*>(&p0.x));
            float2 a1 = __half22float2(*reinterpret_cast<const __half2*>(&p0.y));
            float2 b0 = __half22float2(*reinterpret_cast<const __half2*>(&p1.x));
            float2 b1 = __half22float2(*reinterpret_cast<const __half2*>(&p1.y));
            float2 c0 = __half22float2(*reinterpret_cast<const __half2*>(&p2.x));
            float2 c1 = __half22float2(*reinterpret_cast<const __half2*>(&p2.y));
            float2 d0 = __half22float2(*reinterpret_cast<const __half2*>(&p3.x));
            float2 d1 = __half22float2(*reinterpret_cast<const __half2*>(&p3.y));
            acc.x += (a0.x + b0.x) + (c0.x + d0.x);
            acc.y += (a0.y + b0.y) + (c0.y + d0.y);
            acc.z += (a1.x + b1.x) + (c1.x + d1.x);
            acc.w += (a1.y + b1.y) + (c1.y + d1.y);
        }
        for (; j < cnt; j++) {
            int s = __shfl_sync(0xFFFFFFFFu, sv, j);
            uint2 p = reinterpret_cast<const uint2*>(g_bufH + (size_t)s * DIM)[lane];
            float2 a0 = __half22float2(*reinterpret_cast<const __half2*>(&p.x));
            float2 a1 = __half22float2(*reinterpret_cast<const __half2*>(&p.y));
            acc.x += a0.x; acc.y += a0.y; acc.z += a1.x; acc.w += a1.y;
        }
    }

    float dd = g_dinv[v];
    acc.x *= dd; acc.y *= dd; acc.z *= dd; acc.w *= dd;
    reinterpret_cast<float4*>(g_bufB + (size_t)v * DIM)[lane] = acc;
}

// ===========================================================================
// Host launcher
// ===========================================================================
extern "C" void kernel_launch(void* const* d_in, const int* in_sizes, int n_in,
                              void* d_out, int out_size) {
    const float* x      = (const float*)d_in[0];
    const int*   ei     = (const int*)d_in[1];
    const float* action = (const float*)d_in[2];
    const float* w1     = (const float*)d_in[3];
    const float* b1     = (const float*)d_in[4];
    const float* w2     = (const float*)d_in[5];
    const float* b2     = (const float*)d_in[6];
    const float* fw1    = (const float*)d_in[7];
    const float* fb1    = (const float*)d_in[8];
    const float* fw2    = (const float*)d_in[9];
    const float* fb2    = (const float*)d_in[10];

    int N = in_sizes[0] / DIM;
    int E = in_sizes[1] / 2;

    int nb256       = (N + 255) / 256;
    int eb256       = (E + 255) / 256;
    int gemm_blocks = (N + 127) / 128;
    int agg_blocks  = (int)(((long long)N * 32 + 255) / 256);

    // ---- CSR build + dinv ----
    k_zero_deg <<<nb256, 256>>>(N);
    k_count_deg<<<eb256, 256>>>(ei, E, N);
    k_scan1    <<<nb256, 256>>>(N);          // also computes dinv
    k_scan2    <<<1, 1024>>>(nb256);
    k_scan3    <<<nb256, 256>>>(N, E);
    k_fill     <<<eb256, 256>>>(ei, E, N);

    // ---- GCN layer 1 ----  yH = half((x@W1)*dinv); aggregate -> bufB
    k_sgemm    <<<gemm_blocks, 256>>>(x, 0, nullptr, w1, nullptr,
                                      N, DIM,
                                      nullptr, nullptr, nullptr, nullptr);
    k_aggregate<<<agg_blocks, 256>>>(N);

    // ---- GCN layer 2 ----  yH = half((relu(bufB+b1)@W2)*dinv); aggregate -> bufB
    k_sgemm    <<<gemm_blocks, 256>>>(nullptr, 2, nullptr, w2, b1,
                                      N, DIM,
                                      nullptr, nullptr, nullptr, nullptr);
    k_aggregate<<<agg_blocks, 256>>>(N);

    // ---- MLP head ----  q = relu([relu(bufB+b2), action]@fw1 + fb1) . fw2 + fb2
    k_sgemm<<<gemm_blocks, 256>>>(nullptr, 2, action, fw1, b2,
                                  N, DIM + 16,
                                  fb1, fw2, fb2, (float*)d_out);
}